// round 4
// baseline (speedup 1.0000x reference)
#include <cuda_runtime.h>
#include <math.h>

#define D      2048
#define NS     8
#define BSZ    16384
#define TWOD   (2*D)
#define SLICES 32            // 64 cols per slice

// output layout: read [B,D] | attn [B,8] | alpha [1] | new_state [8,D] | new_fast [8,D]
#define OFF_READ   0
#define OFF_ATTN   ((size_t)BSZ * D)
#define OFF_ALPHA  (OFF_ATTN + (size_t)BSZ * NS)
#define OFF_NS     (OFF_ALPHA + 1)
#define OFF_NF     (OFF_NS + (size_t)NS * D)

// ---------------- device scratch (static, no allocs) ----------------
__device__ float g_S[NS * D];        // state + fast
__device__ float g_Keq[NS * D];      // keys @ Wr
__device__ float g_cq[NS];           // keys @ br
__device__ float g_sWc[NS];          // S @ Wc[0, D:2D]
__device__ float g_M1[NS * D];       // attn.T @ (h + nm)
__device__ float g_G[NS * NS];       // attn.T @ attn
__device__ float g_asum[NS];         // sum_b attn
__device__ float g_sadd;             // sum_b sigmoid(ctrl0)
__device__ float g_delta[NS * D];    // partial delta
__device__ float g_part[(size_t)BSZ * 9 * SLICES];  // per-slice partial dots

// ---------------- prep1: S = state + fast ; zero accumulators ----------------
__global__ void k_prep1(const float* __restrict__ state, const float* __restrict__ fast) {
    int i = blockIdx.x * blockDim.x + threadIdx.x;   // 0..16383
    g_S[i]     = state[i] + fast[i];
    g_Keq[i]   = 0.f;
    g_M1[i]    = 0.f;
    g_delta[i] = 0.f;
    if (i < NS * NS) g_G[i] = 0.f;
    if (i < NS)      g_asum[i] = 0.f;
    if (i == 0)      g_sadd = 0.f;
}

// ---------------- keq: Keq[s,i] = sum_j keys[s,j] * Wr[j,i] ----------------
__global__ void k_keq(const float* __restrict__ keys, const float* __restrict__ Wr) {
    __shared__ float ks[NS][128];
    int t = threadIdx.x;
    int j0 = blockIdx.y * 128;
    int i  = blockIdx.x * 256 + t;
    for (int idx = t; idx < NS * 128; idx += 256)
        ks[idx >> 7][idx & 127] = keys[(idx >> 7) * D + j0 + (idx & 127)];
    __syncthreads();
    float acc[NS];
#pragma unroll
    for (int s = 0; s < NS; s++) acc[s] = 0.f;
    for (int jj = 0; jj < 128; jj++) {
        float w = Wr[(size_t)(j0 + jj) * D + i];
#pragma unroll
        for (int s = 0; s < NS; s++) acc[s] += ks[s][jj] * w;
    }
#pragma unroll
    for (int s = 0; s < NS; s++) atomicAdd(&g_Keq[s * D + i], acc[s]);
}

// ---------------- prep2: cq[s] = keys[s].br ; sWc[s] = S[s].Wc[0,D:] ----------------
__global__ void k_prep2(const float* __restrict__ keys, const float* __restrict__ br,
                        const float* __restrict__ Wc) {
    __shared__ float rbuf[8];
    int s = blockIdx.x >> 1;
    int which = blockIdx.x & 1;
    const float* a = which ? (g_S + s * D) : (keys + s * D);
    const float* w = which ? (Wc + D) : br;
    float acc = 0.f;
    for (int i = threadIdx.x; i < D; i += 256) acc += a[i] * w[i];
#pragma unroll
    for (int off = 16; off; off >>= 1) acc += __shfl_xor_sync(0xffffffffu, acc, off);
    if ((threadIdx.x & 31) == 0) rbuf[threadIdx.x >> 5] = acc;
    __syncthreads();
    if (threadIdx.x == 0) {
        float tot = 0.f;
#pragma unroll
        for (int k = 0; k < 8; k++) tot += rbuf[k];
        if (which) g_sWc[s] = tot; else g_cq[s] = tot;
    }
}

// ---------------- P1: per-warp-slice partial dots (no barriers) ----------------
// warp gw: slice = gw & 31 (64 cols), rowgroup = gw >> 5; processes row pairs.
// partials: 8 slot logits + h.Wc0, stored to g_part[b][v][slice].
__global__ __launch_bounds__(256)
void k_part(const float* __restrict__ h, const float* __restrict__ Wc) {
    int lane = threadIdx.x & 31;
    int gw = blockIdx.x * 8 + (threadIdx.x >> 5);
    int slice = gw & (SLICES - 1);
    int rg = gw >> 5;
    int nGroups = (gridDim.x * 8) >> 5;
    int col0 = slice * 64 + lane * 2;

    float2 kq[NS];
#pragma unroll
    for (int s = 0; s < NS; s++)
        kq[s] = *(const float2*)(g_Keq + s * D + col0);
    float2 wv = *(const float2*)(Wc + col0);
    bool hi = (lane & 16) != 0;

    for (int rb = rg; rb < BSZ / 2; rb += nGroups) {
        int b = rb * 2;
        float2 ha = *(const float2*)(h + (size_t)b * D + col0);
        float2 hb = *(const float2*)(h + (size_t)(b + 1) * D + col0);
        float pa[9], pb[9];
#pragma unroll
        for (int s = 0; s < NS; s++) {
            pa[s] = kq[s].x * ha.x + kq[s].y * ha.y;
            pb[s] = kq[s].x * hb.x + kq[s].y * hb.y;
        }
        pa[8] = wv.x * ha.x + wv.y * ha.y;
        pb[8] = wv.x * hb.x + wv.y * hb.y;
        float mg[9];
#pragma unroll
        for (int k = 0; k < 9; k++) {
            float send = hi ? pa[k] : pb[k];
            float got  = __shfl_xor_sync(0xffffffffu, send, 16);
            float keep = hi ? pb[k] : pa[k];
            mg[k] = keep + got;    // lo half: row a, hi half: row b
        }
#pragma unroll
        for (int d = 8; d; d >>= 1) {
#pragma unroll
            for (int k = 0; k < 9; k++)
                mg[k] += __shfl_xor_sync(0xffffffffu, mg[k], d);
        }
        if (lane == 0) {
#pragma unroll
            for (int v = 0; v < 9; v++)
                g_part[(size_t)b * (9 * SLICES) + v * SLICES + slice] = mg[v];
        } else if (lane == 16) {
#pragma unroll
            for (int v = 0; v < 9; v++)
                g_part[(size_t)(b + 1) * (9 * SLICES) + v * SLICES + slice] = mg[v];
        }
    }
}

// ---------------- P2: allreduce + softmax per row; G/asum/sadd ----------------
__global__ __launch_bounds__(256)
void k_soft(const float* __restrict__ bc, float* __restrict__ attn_out) {
    __shared__ float a_sm[8][8];
    int w = threadIdx.x >> 5, lane = threadIdx.x & 31;
    float4 c0 = *(const float4*)(g_cq);
    float4 c1 = *(const float4*)(g_cq + 4);
    float cq[8] = {c0.x,c0.y,c0.z,c0.w,c1.x,c1.y,c1.z,c1.w};
    float4 w0 = *(const float4*)(g_sWc);
    float4 w1 = *(const float4*)(g_sWc + 4);
    float swc[8] = {w0.x,w0.y,w0.z,w0.w,w1.x,w1.y,w1.z,w1.w};
    float bc0 = bc[0];
    float gacc0 = 0.f, gacc1 = 0.f, asl = 0.f, saddl = 0.f;
    int i0 = (lane >> 3), j0 = (lane & 7);       // G entry `lane`
    int i1 = i0 + 4;                              // G entry lane+32

    for (int b = blockIdx.x * 8 + w; b < BSZ; b += gridDim.x * 8) {
        const float* base = g_part + (size_t)b * (9 * SLICES);
        float mg[9];
#pragma unroll
        for (int v = 0; v < 9; v++) mg[v] = base[v * SLICES + lane];
#pragma unroll
        for (int d = 16; d; d >>= 1) {
#pragma unroll
            for (int v = 0; v < 9; v++)
                mg[v] += __shfl_xor_sync(0xffffffffu, mg[v], d);
        }
        float lg[8], m = -1e30f;
#pragma unroll
        for (int v = 0; v < 8; v++) { lg[v] = mg[v] + cq[v]; m = fmaxf(m, lg[v]); }
        float e[8], se = 0.f;
#pragma unroll
        for (int v = 0; v < 8; v++) { e[v] = expf(lg[v] - m); se += e[v]; }
        float inv = 1.f / se;
        float aw = 0.f;
#pragma unroll
        for (int v = 0; v < 8; v++) { e[v] *= inv; aw += e[v] * swc[v]; }
        if (lane == 0) {
            saddl += 1.f / (1.f + expf(-(mg[8] + aw + bc0)));
#pragma unroll
            for (int v = 0; v < 8; v++) a_sm[w][v] = e[v];
        }
        __syncwarp();
        if (lane < 8) {
            float av = a_sm[w][lane];
            attn_out[(size_t)b * NS + lane] = av;
            asl += av;
        }
        gacc0 += a_sm[w][i0] * a_sm[w][j0];
        gacc1 += a_sm[w][i1] * a_sm[w][j0];
        __syncwarp();
    }
    atomicAdd(&g_G[lane], gacc0);
    atomicAdd(&g_G[lane + 32], gacc1);
    if (lane < 8) atomicAdd(&g_asum[lane], asl);
    if (lane == 0) atomicAdd(&g_sadd, saddl);
}

// ---------------- P3: streaming — read output + M1 accumulation ----------------
__global__ __launch_bounds__(512)
void k_stream(const float* __restrict__ h, const float* __restrict__ nm,
              const float* __restrict__ attn, float* __restrict__ read_out) {
    extern __shared__ float4 s_sm[];   // [NS][512]
    int t = threadIdx.x;
#pragma unroll
    for (int s = 0; s < NS; s++)
        s_sm[s * 512 + t] = ((const float4*)(g_S + s * D))[t];
    float m1[NS][4];
#pragma unroll
    for (int s = 0; s < NS; s++) { m1[s][0]=0.f; m1[s][1]=0.f; m1[s][2]=0.f; m1[s][3]=0.f; }
    __syncthreads();

    for (int b = blockIdx.x; b < BSZ; b += gridDim.x) {
        float4 hv = ((const float4*)(h  + (size_t)b * D))[t];
        float4 nv = ((const float4*)(nm + (size_t)b * D))[t];
        float4 a0 = ((const float4*)(attn + (size_t)b * NS))[0];
        float4 a1 = ((const float4*)(attn + (size_t)b * NS))[1];
        float aa[8] = {a0.x,a0.y,a0.z,a0.w,a1.x,a1.y,a1.z,a1.w};
        float hn0 = hv.x + nv.x, hn1 = hv.y + nv.y;
        float hn2 = hv.z + nv.z, hn3 = hv.w + nv.w;
        float4 rd = {0.f,0.f,0.f,0.f};
#pragma unroll
        for (int s = 0; s < NS; s++) {
            float as = aa[s];
            float4 sv = s_sm[s * 512 + t];
            m1[s][0] += as * hn0; m1[s][1] += as * hn1;
            m1[s][2] += as * hn2; m1[s][3] += as * hn3;
            rd.x += as * sv.x; rd.y += as * sv.y;
            rd.z += as * sv.z; rd.w += as * sv.w;
        }
        ((float4*)(read_out + (size_t)b * D))[t] = rd;
    }
#pragma unroll
    for (int s = 0; s < NS; s++) {
#pragma unroll
        for (int k = 0; k < 4; k++)
            atomicAdd(&g_M1[s * D + 4 * t + k], m1[s][k]);
    }
}

// ---------------- delta partials: [M1 | G@S] @ Ww^T ----------------
__global__ __launch_bounds__(256)
void k_delta(const float* __restrict__ Ww) {
    __shared__ float u_sm[NS][256];
    __shared__ float gsm[64];
    int t = threadIdx.x;
    int i0 = blockIdx.y * 256;                  // 0..4095
    int ui0 = i0 & (D - 1);
    if (i0 >= D && t < 64) gsm[t] = g_G[t];
    __syncthreads();
    if (i0 < D) {
        for (int idx = t; idx < NS * 256; idx += 256)
            u_sm[idx >> 8][idx & 255] = g_M1[(idx >> 8) * D + ui0 + (idx & 255)];
    } else {
        float sv[NS];
#pragma unroll
        for (int sp = 0; sp < NS; sp++) sv[sp] = g_S[sp * D + ui0 + t];
#pragma unroll
        for (int s = 0; s < NS; s++) {
            float u = 0.f;
#pragma unroll
            for (int sp = 0; sp < NS; sp++) u += gsm[s * NS + sp] * sv[sp];
            u_sm[s][t] = u;
        }
    }
    __syncthreads();
    int o = blockIdx.x * 256 + t;
    float acc[NS];
#pragma unroll
    for (int s = 0; s < NS; s++) acc[s] = 0.f;
    const float* wrow = Ww + (size_t)o * TWOD + i0;
    for (int ii = 0; ii < 256; ii += 4) {
        float4 w = *(const float4*)(wrow + ii);
#pragma unroll
        for (int s = 0; s < NS; s++)
            acc[s] += u_sm[s][ii]*w.x + u_sm[s][ii+1]*w.y + u_sm[s][ii+2]*w.z + u_sm[s][ii+3]*w.w;
    }
#pragma unroll
    for (int s = 0; s < NS; s++) atomicAdd(&g_delta[s * D + o], acc[s]);
}

// ---------------- final: alpha, new_state, new_fast ----------------
__global__ void k_final(const float* __restrict__ bw, const float* __restrict__ state,
                        const float* __restrict__ fast, float* __restrict__ out) {
    int idx = blockIdx.x * 256 + threadIdx.x;   // 16384
    float mean = g_sadd * (1.f / (float)BSZ);
    float alpha = 0.02f + 0.98f * mean;
    alpha = fminf(fmaxf(alpha, 0.f), 1.f);      // ALPHA_BOOST = 1
    int s = idx >> 11, o = idx & (D - 1);
    float delta = g_delta[idx] + g_asum[s] * bw[o];
    out[OFF_NS + idx] = (1.f - alpha) * state[idx] + alpha * delta;
    out[OFF_NF + idx] = 0.95f * fast[idx] + 0.05f * delta;
    if (idx == 0) out[OFF_ALPHA] = alpha;
}

// ---------------- launch ----------------
extern "C" void kernel_launch(void* const* d_in, const int* in_sizes, int n_in,
                              void* d_out, int out_size) {
    const float* h     = (const float*)d_in[0];
    const float* nm    = (const float*)d_in[1];
    const float* keys  = (const float*)d_in[2];
    const float* Wr    = (const float*)d_in[3];
    const float* br    = (const float*)d_in[4];
    const float* Wc    = (const float*)d_in[5];
    const float* bc    = (const float*)d_in[6];
    const float* Ww    = (const float*)d_in[7];
    const float* bw    = (const float*)d_in[8];
    const float* state = (const float*)d_in[9];
    const float* fast  = (const float*)d_in[10];
    float* out = (float*)d_out;

    const int SMEM_DYN = NS * 512 * sizeof(float4);   // 32KB... (8*512*16 = 64KB)
    cudaFuncSetAttribute(k_stream, cudaFuncAttributeMaxDynamicSharedMemorySize, SMEM_DYN);

    k_prep1<<<64, 256>>>(state, fast);
    k_keq<<<dim3(8, 16), 256>>>(keys, Wr);
    k_prep2<<<16, 256>>>(keys, br, Wc);
    k_part<<<1184, 256>>>(h, Wc);                       // 9472 warps: 32 slices x 296 rowgroups
    k_soft<<<512, 256>>>(bc, out + OFF_ATTN);           // 4096 warps: 4 rows each
    k_stream<<<296, 512, SMEM_DYN>>>(h, nm, out + OFF_ATTN, out + OFF_READ);
    k_delta<<<dim3(8, 16), 256>>>(Ww);
    k_final<<<64, 256>>>(bw, state, fast, out);
}